// round 1
// baseline (speedup 1.0000x reference)
#include <cuda_runtime.h>
#include <cuda_bf16.h>

// Problem constants (from reference): B=16, NX=2048, HD=64 -> H=32, T=8192.
#define HD    64
#define T_CTX 8192
#define H_HEADS 32
#define B_SZ  16
#define TCH   1024   // t-chunk per iteration
#define NTHR  256

__global__ __launch_bounds__(NTHR, 1)
void attn_nosoftmax_kernel(const float* __restrict__ q,
                           const float* __restrict__ k,
                           const float* __restrict__ v,
                           const float* __restrict__ pk,   // [B,H,HD,T]  (t contiguous)
                           const float* __restrict__ pv,   // [B,H,T,HD]  (d contiguous)
                           float* __restrict__ out)        // [B, H*HD]
{
    __shared__ float sq[HD];
    __shared__ float sw[TCH];          // 4 KB: w[t] for current chunk
    __shared__ float sred[16 * HD];    // 4 KB: cross-group reduction
    __shared__ float s_wcur;

    const int tid = threadIdx.x;
    const int bh  = blockIdx.x;                       // b*H + h
    const float* Kb = pk + (size_t)bh * HD * T_CTX;
    const float* Vb = pv + (size_t)bh * T_CTX * HD;
    const float* qb = q  + (size_t)bh * HD;           // NX == H*HD
    const float* kb = k  + (size_t)bh * HD;

    if (tid < HD) sq[tid] = qb[tid];
    __syncthreads();

    // current-token weight: wcur = dot(q, k_cur)
    if (tid < 32) {
        float p = sq[tid] * kb[tid] + sq[tid + 32] * kb[tid + 32];
        #pragma unroll
        for (int off = 16; off > 0; off >>= 1)
            p += __shfl_down_sync(0xffffffffu, p, off);
        if (tid == 0) s_wcur = p;
    }

    const int g = tid >> 4;   // 0..15 : t-group for phase 2
    const int x = tid & 15;   // 0..15 : float4 column within the 64-wide row
    float4 acc = make_float4(0.f, 0.f, 0.f, 0.f);

    #pragma unroll 1
    for (int c = 0; c < T_CTX / TCH; c++) {
        const int t0 = c * TCH;

        // ---- phase 1: w[t] = sum_d q[d] * K[d, t]  (each thread owns 4 t's) ----
        float4 wv = make_float4(0.f, 0.f, 0.f, 0.f);
        const float* kp = Kb + t0 + tid * 4;
        #pragma unroll
        for (int d = 0; d < HD; d++) {
            float4 kk = *(const float4*)(kp + (size_t)d * T_CTX);
            float qd = sq[d];
            wv.x = fmaf(qd, kk.x, wv.x);
            wv.y = fmaf(qd, kk.y, wv.y);
            wv.z = fmaf(qd, kk.z, wv.z);
            wv.w = fmaf(qd, kk.w, wv.w);
        }
        __syncthreads();                 // prior chunk's phase-2 reads of sw done
        *(float4*)(sw + tid * 4) = wv;
        __syncthreads();                 // sw visible to all

        // ---- phase 2: acc[d] += w[t] * V[t, d] ----
        // group g handles t = t0+g, t0+g+16, ...; 16 lanes cover 64 floats/row.
        const float* vp = Vb + (size_t)t0 * HD + x * 4;
        #pragma unroll 8
        for (int j = g; j < TCH; j += 16) {
            float  wt = sw[j];
            float4 vv = *(const float4*)(vp + (size_t)j * HD);
            acc.x = fmaf(wt, vv.x, acc.x);
            acc.y = fmaf(wt, vv.y, acc.y);
            acc.z = fmaf(wt, vv.z, acc.z);
            acc.w = fmaf(wt, vv.w, acc.w);
        }
    }

    // ---- reduce 16 partial groups, add current-token term, write out ----
    __syncthreads();
    *(float4*)(&sred[g * HD + x * 4]) = acc;
    __syncthreads();
    if (tid < HD) {
        float s = 0.f;
        #pragma unroll
        for (int gg = 0; gg < 16; gg++) s += sred[gg * HD + tid];
        s = fmaf(s_wcur, v[(size_t)bh * HD + tid], s);
        out[(size_t)bh * HD + tid] = s;
    }
}

extern "C" void kernel_launch(void* const* d_in, const int* in_sizes, int n_in,
                              void* d_out, int out_size) {
    const float* q  = (const float*)d_in[0];
    const float* k  = (const float*)d_in[1];
    const float* v  = (const float*)d_in[2];
    const float* pk = (const float*)d_in[3];
    const float* pv = (const float*)d_in[4];
    float* out = (float*)d_out;

    attn_nosoftmax_kernel<<<B_SZ * H_HEADS, NTHR>>>(q, k, v, pk, pv, out);
}

// round 2
// speedup vs baseline: 1.0614x; 1.0614x over previous
#include <cuda_runtime.h>
#include <cuda_bf16.h>

// B=16, NX=2048, HD=64 -> H=32, T=8192. No softmax.
#define HD      64
#define T_CTX   8192
#define H_HEADS 32
#define B_SZ    16
#define NTHR    256
#define NWARP   (NTHR / 32)
#define T_PER_WARP (T_CTX / NWARP)   // 1024

__global__ __launch_bounds__(NTHR, 4)
void attn_nosoftmax_kernel(const float* __restrict__ q,
                           const float* __restrict__ k,
                           const float* __restrict__ v,
                           const float* __restrict__ pk,   // [B,H,HD,T]  (t contiguous)
                           const float* __restrict__ pv,   // [B,H,T,HD]  (d contiguous)
                           float* __restrict__ out)        // [B, H*HD]
{
    __shared__ float sq[HD];
    __shared__ float sred[NWARP][HD];   // 2 KB cross-warp reduction
    __shared__ float s_wcur;

    const int tid  = threadIdx.x;
    const int lane = tid & 31;
    const int wid  = tid >> 5;
    const int bh   = blockIdx.x;                      // b*H + h
    const float* Kb = pk + (size_t)bh * HD * T_CTX;
    const float* Vb = pv + (size_t)bh * T_CTX * HD;
    const float* qb = q  + (size_t)bh * HD;
    const float* kb = k  + (size_t)bh * HD;

    if (tid < HD) sq[tid] = qb[tid];

    // current-token weight: wcur = dot(q, k_cur) (warp 0, overlapped)
    if (wid == 0) {
        float p = qb[lane] * kb[lane] + qb[lane + 32] * kb[lane + 32];
        #pragma unroll
        for (int off = 16; off > 0; off >>= 1)
            p += __shfl_down_sync(0xffffffffu, p, off);
        if (lane == 0) s_wcur = p;
    }
    __syncthreads();   // sq visible to all warps

    // Warp-private t-strip: [wid*1024, wid*1024+1024), processed 32 t's/tile.
    const int tbase = wid * T_PER_WARP;
    float2 acc = make_float2(0.f, 0.f);   // lane owns d = 2*lane, 2*lane+1

    #pragma unroll 1
    for (int tile = 0; tile < T_PER_WARP / 32; tile++) {
        const int t0 = tbase + tile * 32;

        // Phase A: w = sum_d q[d] * K[d, t0+lane]   (coalesced 128B per d)
        float wv = 0.f;
        const float* kp = Kb + t0 + lane;
        #pragma unroll 16
        for (int d = 0; d < HD; d++)
            wv = fmaf(sq[d], kp[(size_t)d * T_CTX], wv);

        // Phase B: acc[d] += w[j] * V[t0+j, d]; w[j] lives in lane j.
        const float2* vp = (const float2*)(Vb + (size_t)t0 * HD) + lane;
        #pragma unroll 8
        for (int j = 0; j < 32; j++) {
            float  wj = __shfl_sync(0xffffffffu, wv, j);
            float2 vv = vp[j * (HD / 2)];
            acc.x = fmaf(wj, vv.x, acc.x);
            acc.y = fmaf(wj, vv.y, acc.y);
        }
    }

    // Cross-warp reduction, add current-token term, write.
    sred[wid][2 * lane]     = acc.x;
    sred[wid][2 * lane + 1] = acc.y;
    __syncthreads();
    if (tid < HD) {
        float s = 0.f;
        #pragma unroll
        for (int w = 0; w < NWARP; w++) s += sred[w][tid];
        s = fmaf(s_wcur, v[(size_t)bh * HD + tid], s);
        out[(size_t)bh * HD + tid] = s;
    }
}

extern "C" void kernel_launch(void* const* d_in, const int* in_sizes, int n_in,
                              void* d_out, int out_size) {
    const float* q  = (const float*)d_in[0];
    const float* k  = (const float*)d_in[1];
    const float* v  = (const float*)d_in[2];
    const float* pk = (const float*)d_in[3];
    const float* pv = (const float*)d_in[4];
    float* out = (float*)d_out;

    attn_nosoftmax_kernel<<<B_SZ * H_HEADS, NTHR>>>(q, k, v, pk, pv, out);
}

// round 3
// speedup vs baseline: 1.1340x; 1.0684x over previous
#include <cuda_runtime.h>
#include <cuda_bf16.h>

// B=16, NX=2048, HD=64 -> H=32, T=8192. No softmax.
#define HD      64
#define T_CTX   8192
#define H_HEADS 32
#define B_SZ    16
#define NBH     (B_SZ * H_HEADS)      // 512
#define SPLITS  2                     // t-range splits per (b,h)
#define NTHR    128                   // 4 warps
#define NWARP   (NTHR / 32)
#define T_SPLIT (T_CTX / SPLITS)      // 4096
#define T_WARP  (T_SPLIT / NWARP)     // 1024
#define TILE    128                   // t's per warp-iteration

// partial outputs: [NBH * SPLITS][HD]
__device__ float g_part[NBH * SPLITS * HD];

__global__ __launch_bounds__(NTHR, 8)
void attn_main_kernel(const float* __restrict__ q,
                      const float* __restrict__ pk,   // [B,H,HD,T]  (t contiguous)
                      const float* __restrict__ pv)   // [B,H,T,HD]  (d contiguous)
{
    __shared__ float sq[HD];
    __shared__ float sred[NWARP][HD];

    const int tid  = threadIdx.x;
    const int lane = tid & 31;
    const int wid  = tid >> 5;
    const int bh   = blockIdx.x >> 1;       // 0..511
    const int half = blockIdx.x & 1;        // 0..1

    const float* Kb = pk + (size_t)bh * HD * T_CTX;
    const float* Vb = pv + (size_t)bh * T_CTX * HD;

    if (tid < HD) sq[tid] = q[(size_t)bh * HD + tid];
    __syncthreads();

    const int tbase = half * T_SPLIT + wid * T_WARP;
    float2 acc = make_float2(0.f, 0.f);     // lane owns d = 2*lane, 2*lane+1

    #pragma unroll 1
    for (int tile = 0; tile < T_WARP / TILE; tile++) {
        const int t0 = tbase + tile * TILE;

        // Phase A: w[t0 + 4*lane + i] = sum_d q[d]*K[d, .]  (float4 per lane)
        float4 wv = make_float4(0.f, 0.f, 0.f, 0.f);
        const float4* kp = (const float4*)(Kb + t0) + lane;
        #pragma unroll 8
        for (int d = 0; d < HD; d++) {
            float4 kk = kp[(size_t)d * (T_CTX / 4)];
            float qd = sq[d];
            wv.x = fmaf(qd, kk.x, wv.x);
            wv.y = fmaf(qd, kk.y, wv.y);
            wv.z = fmaf(qd, kk.z, wv.z);
            wv.w = fmaf(qd, kk.w, wv.w);
        }

        // Phase B: acc[d] += w[t]*V[t,d]; w for t0+4*l+i lives in lane l comp i.
        const float2* vp = (const float2*)(Vb + (size_t)t0 * HD) + lane;
        #pragma unroll 4
        for (int l = 0; l < 32; l++) {
            float w0 = __shfl_sync(0xffffffffu, wv.x, l);
            float w1 = __shfl_sync(0xffffffffu, wv.y, l);
            float w2 = __shfl_sync(0xffffffffu, wv.z, l);
            float w3 = __shfl_sync(0xffffffffu, wv.w, l);
            float2 v0 = vp[(4 * l + 0) * (HD / 2)];
            float2 v1 = vp[(4 * l + 1) * (HD / 2)];
            float2 v2 = vp[(4 * l + 2) * (HD / 2)];
            float2 v3 = vp[(4 * l + 3) * (HD / 2)];
            acc.x = fmaf(w0, v0.x, acc.x);  acc.y = fmaf(w0, v0.y, acc.y);
            acc.x = fmaf(w1, v1.x, acc.x);  acc.y = fmaf(w1, v1.y, acc.y);
            acc.x = fmaf(w2, v2.x, acc.x);  acc.y = fmaf(w2, v2.y, acc.y);
            acc.x = fmaf(w3, v3.x, acc.x);  acc.y = fmaf(w3, v3.y, acc.y);
        }
    }

    // Cross-warp reduction -> partial slice
    sred[wid][2 * lane]     = acc.x;
    sred[wid][2 * lane + 1] = acc.y;
    __syncthreads();
    if (tid < HD) {
        float s = 0.f;
        #pragma unroll
        for (int w = 0; w < NWARP; w++) s += sred[w][tid];
        g_part[(size_t)blockIdx.x * HD + tid] = s;
    }
}

// out[bh,d] = part0 + part1 + dot(q_bh, k_bh) * v[bh,d]
__global__ __launch_bounds__(HD)
void attn_combine_kernel(const float* __restrict__ q,
                         const float* __restrict__ k,
                         const float* __restrict__ v,
                         float* __restrict__ out)
{
    __shared__ float s_wcur;
    const int bh = blockIdx.x;
    const int d  = threadIdx.x;
    const int lane = d & 31;

    // dot(q,k) over 64 elems: warp 0 reduces, others idle briefly
    if (d < 32) {
        size_t base = (size_t)bh * HD;
        float p = q[base + lane] * k[base + lane]
                + q[base + lane + 32] * k[base + lane + 32];
        #pragma unroll
        for (int off = 16; off > 0; off >>= 1)
            p += __shfl_down_sync(0xffffffffu, p, off);
        if (lane == 0) s_wcur = p;
    }
    __syncthreads();

    size_t o = (size_t)bh * HD + d;
    float s = g_part[(size_t)(2 * bh) * HD + d]
            + g_part[(size_t)(2 * bh + 1) * HD + d];
    out[o] = fmaf(s_wcur, v[o], s);
}

extern "C" void kernel_launch(void* const* d_in, const int* in_sizes, int n_in,
                              void* d_out, int out_size) {
    const float* q  = (const float*)d_in[0];
    const float* k  = (const float*)d_in[1];
    const float* v  = (const float*)d_in[2];
    const float* pk = (const float*)d_in[3];
    const float* pv = (const float*)d_in[4];
    float* out = (float*)d_out;

    attn_main_kernel<<<NBH * SPLITS, NTHR>>>(q, pk, pv);
    attn_combine_kernel<<<NBH, HD>>>(q, k, v, out);
}

// round 4
// speedup vs baseline: 1.1528x; 1.0166x over previous
#include <cuda_runtime.h>
#include <cuda_bf16.h>

// B=16, NX=2048, HD=64 -> H=32, T=8192. No softmax.
#define HD      64
#define T_CTX   8192
#define H_HEADS 32
#define B_SZ    16
#define NBH     (B_SZ * H_HEADS)      // 512
#define SPLITS  2
#define NTHR    128                   // 4 warps
#define NWARP   (NTHR / 32)
#define T_SPLIT (T_CTX / SPLITS)      // 4096
#define T_WARP  (T_SPLIT / NWARP)     // 1024
#define TILE    128                   // t's per warp-iteration
#define NTILE   (T_WARP / TILE)       // 8

// partial outputs: [NBH * SPLITS][HD]
__device__ float g_part[NBH * SPLITS * HD];

// ---- phase A: w[t0 + 4*lane + i] = sum_d q[d] * K[d, t0+4*lane+i] ----
__device__ __forceinline__ float4 phaseA(const float* __restrict__ Kb,
                                         const float* __restrict__ sq,
                                         int t0, int lane)
{
    float4 wv = make_float4(0.f, 0.f, 0.f, 0.f);
    const float4* kp = (const float4*)(Kb + t0) + lane;
    #pragma unroll
    for (int d = 0; d < HD; d++) {
        float4 kk = kp[(size_t)d * (T_CTX / 4)];
        float qd = sq[d];
        wv.x = fmaf(qd, kk.x, wv.x);
        wv.y = fmaf(qd, kk.y, wv.y);
        wv.z = fmaf(qd, kk.z, wv.z);
        wv.w = fmaf(qd, kk.w, wv.w);
    }
    return wv;
}

__global__ __launch_bounds__(NTHR, 8)
void attn_main_kernel(const float* __restrict__ q,
                      const float* __restrict__ pk,   // [B,H,HD,T]  (t contiguous)
                      const float* __restrict__ pv)   // [B,H,T,HD]  (d contiguous)
{
    __shared__ float sq[HD];
    __shared__ float sw[2][NWARP][TILE];      // double-buffered per-warp w
    __shared__ float sred[2 * NWARP][HD];

    const int tid  = threadIdx.x;
    const int lane = tid & 31;
    const int wid  = tid >> 5;
    const int par  = lane >> 4;               // row parity within step
    const int dx   = lane & 15;               // d-quad index
    const int bh   = blockIdx.x >> 1;
    const int half = blockIdx.x & 1;

    const float* Kb = pk + (size_t)bh * HD * T_CTX;
    const float* Vb = pv + (size_t)bh * T_CTX * HD;

    if (tid < HD) sq[tid] = q[(size_t)bh * HD + tid];
    __syncthreads();

    const int tbase = half * T_SPLIT + wid * T_WARP;
    float4 acc = make_float4(0.f, 0.f, 0.f, 0.f);  // lane: d = 4*dx..4*dx+3, rows of parity par

    // prologue: w for tile 0 into buffer 0
    {
        float4 w0 = phaseA(Kb, sq, tbase, lane);
        *(float4*)(&sw[0][wid][lane * 4]) = w0;
    }
    __syncwarp();

    int buf = 0;
    #pragma unroll 1
    for (int tile = 0; tile < NTILE; tile++) {
        const int t0 = tbase + tile * TILE;

        // pipeline: compute w(tile+1) while B consumes w(tile)
        float4 wn;
        if (tile + 1 < NTILE)
            wn = phaseA(Kb, sq, t0 + TILE, lane);

        // phase B: rows r = 2*jj + par; lane loads float4 of V at d=4*dx.
        const float4* vp = (const float4*)(Vb + (size_t)t0 * HD) + dx;
        const float* wrow = &sw[buf][wid][par];
        #pragma unroll 8
        for (int jj = 0; jj < TILE / 2; jj++) {
            float  wt = wrow[2 * jj];
            float4 vv = vp[(2 * jj + par) * (HD / 4)];
            acc.x = fmaf(wt, vv.x, acc.x);
            acc.y = fmaf(wt, vv.y, acc.y);
            acc.z = fmaf(wt, vv.z, acc.z);
            acc.w = fmaf(wt, vv.w, acc.w);
        }

        if (tile + 1 < NTILE) {
            *(float4*)(&sw[buf ^ 1][wid][lane * 4]) = wn;
        }
        __syncwarp();
        buf ^= 1;
    }

    // reduction: 8 partials (4 warps x 2 parities) per d
    *(float4*)(&sred[wid * 2 + par][dx * 4]) = acc;
    __syncthreads();
    if (tid < HD) {
        float s = 0.f;
        #pragma unroll
        for (int w = 0; w < 2 * NWARP; w++) s += sred[w][tid];
        g_part[(size_t)blockIdx.x * HD + tid] = s;
    }
}

// out[bh,d] = part0 + part1 + dot(q_bh,k_bh) * v[bh,d]
__global__ __launch_bounds__(HD)
void attn_combine_kernel(const float* __restrict__ q,
                         const float* __restrict__ k,
                         const float* __restrict__ v,
                         float* __restrict__ out)
{
    __shared__ float s_wcur;
    const int bh = blockIdx.x;
    const int d  = threadIdx.x;
    const int lane = d & 31;

    if (d < 32) {
        size_t base = (size_t)bh * HD;
        float p = q[base + lane] * k[base + lane]
                + q[base + lane + 32] * k[base + lane + 32];
        #pragma unroll
        for (int off = 16; off > 0; off >>= 1)
            p += __shfl_down_sync(0xffffffffu, p, off);
        if (lane == 0) s_wcur = p;
    }
    __syncthreads();

    size_t o = (size_t)bh * HD + d;
    float s = g_part[(size_t)(2 * bh) * HD + d]
            + g_part[(size_t)(2 * bh + 1) * HD + d];
    out[o] = fmaf(s_wcur, v[o], s);
}

extern "C" void kernel_launch(void* const* d_in, const int* in_sizes, int n_in,
                              void* d_out, int out_size) {
    const float* q  = (const float*)d_in[0];
    const float* k  = (const float*)d_in[1];
    const float* v  = (const float*)d_in[2];
    const float* pk = (const float*)d_in[3];
    const float* pv = (const float*)d_in[4];
    float* out = (float*)d_out;

    attn_main_kernel<<<NBH * SPLITS, NTHR>>>(q, pk, pv);
    attn_combine_kernel<<<NBH, HD>>>(q, k, v, out);
}